// round 8
// baseline (speedup 1.0000x reference)
#include <cuda_runtime.h>
#include <cstdint>
#include <math.h>

#define T_TOK   8192
#define H_DIM   1024
#define F_DIM   4096
#define E_NUM   8
#define A_NUM   (2 * T_TOK)

// ---------------- scratch (known-good R1 set) --------------------------------
__device__ int   d_counts[E_NUM];
__device__ int   d_cursor[E_NUM];
__device__ int   d_off[E_NUM];
__device__ int   d_eidx[A_NUM];
__device__ float d_wt[A_NUM];
__device__ int   d_tok[A_NUM];
__device__ int   d_slot[A_NUM];
__device__ float d_hbuf[(size_t)A_NUM * F_DIM];
__device__ float d_ybuf[(size_t)A_NUM * H_DIM];

// ---------------- PTX --------------------------------------------------------
__device__ __forceinline__ void mma_tf32(float* c, const uint32_t* a, uint32_t b0, uint32_t b1) {
    asm volatile("mma.sync.aligned.m16n8k8.row.col.f32.tf32.tf32.f32 "
                 "{%0,%1,%2,%3}, {%4,%5,%6,%7}, {%8,%9}, {%0,%1,%2,%3};"
                 : "+f"(c[0]), "+f"(c[1]), "+f"(c[2]), "+f"(c[3])
                 : "r"(a[0]), "r"(a[1]), "r"(a[2]), "r"(a[3]), "r"(b0), "r"(b1));
}
__device__ __forceinline__ void split_tf32(float x, uint32_t& hi, uint32_t& lo) {
    uint32_t h;
    asm("cvt.rna.tf32.f32 %0, %1;" : "=r"(h) : "f"(x));
    float r = x - __uint_as_float(h);
    asm("cvt.rna.tf32.f32 %0, %1;" : "=r"(lo) : "f"(r));
    hi = h;
}

// ---------------- small kernels (R1 verbatim) --------------------------------
__global__ void init_kernel() {
    int i = threadIdx.x;
    if (i < E_NUM) { d_counts[i] = 0; d_cursor[i] = 0; }
}

__global__ void router_kernel(const float* __restrict__ x,
                              const float* __restrict__ rw,
                              const float* __restrict__ rb) {
    int warp = (blockIdx.x * blockDim.x + threadIdx.x) >> 5;
    int lane = threadIdx.x & 31;
    if (warp >= T_TOK) return;
    const float* xr = x + (size_t)warp * H_DIM;
    float acc[E_NUM];
#pragma unroll
    for (int e = 0; e < E_NUM; e++) acc[e] = 0.f;
    for (int k = lane; k < H_DIM; k += 32) {
        float xv = xr[k];
        const float* r = rw + (size_t)k * E_NUM;
#pragma unroll
        for (int e = 0; e < E_NUM; e++) acc[e] += xv * r[e];
    }
#pragma unroll
    for (int off = 16; off; off >>= 1)
#pragma unroll
        for (int e = 0; e < E_NUM; e++)
            acc[e] += __shfl_down_sync(0xffffffffu, acc[e], off);
    if (lane == 0) {
        float l[E_NUM];
#pragma unroll
        for (int e = 0; e < E_NUM; e++) l[e] = acc[e] + rb[e];
        int i0 = 0;
#pragma unroll
        for (int e = 1; e < E_NUM; e++) if (l[e] > l[i0]) i0 = e;
        int i1 = -1;
#pragma unroll
        for (int e = 0; e < E_NUM; e++)
            if (e != i0 && (i1 < 0 || l[e] > l[i1])) i1 = e;
        float m  = l[i0];
        float p1 = __expf(l[i1] - m);
        float s  = 1.f + p1;
        d_eidx[2 * warp + 0] = i0;  d_wt[2 * warp + 0] = 1.f / s;
        d_eidx[2 * warp + 1] = i1;  d_wt[2 * warp + 1] = p1 / s;
        atomicAdd(&d_counts[i0], 1);
        atomicAdd(&d_counts[i1], 1);
    }
}

__global__ void offsets_kernel() {
    if (threadIdx.x == 0) {
        int acc = 0;
        for (int e = 0; e < E_NUM; e++) { d_off[e] = acc; acc += d_counts[e]; }
    }
}

__global__ void scatter_kernel() {
    int t = blockIdx.x * blockDim.x + threadIdx.x;
    if (t >= T_TOK) return;
#pragma unroll
    for (int j = 0; j < 2; j++) {
        int e   = d_eidx[2 * t + j];
        int pos = d_off[e] + atomicAdd(&d_cursor[e], 1);
        d_tok[pos] = t;
        d_slot[2 * t + j] = pos;
    }
}

// ---------------- grouped GEMM: pre-split tf32 planes + reg prefetch ---------
__device__ __forceinline__ float gelu_tanh(float v) {
    float c = 0.7978845608028654f * (v + 0.044715f * v * v * v);
    return 0.5f * v * (1.f + tanhf(c));
}

#define BK      16
#define LDS_PAD 136

template <bool G1>
__global__ __launch_bounds__(256, 2) void moe_gemm(const float* __restrict__ A_in,
                                                   const float* __restrict__ W,
                                                   const float* __restrict__ bias) {
    constexpr int K_TOT = G1 ? H_DIM : F_DIM;
    constexpr int N_TOT = G1 ? F_DIM : H_DIM;
    constexpr int NCH   = K_TOT / BK;

    int e   = blockIdx.z;
    int cnt = d_counts[e];
    int m0  = blockIdx.y * 128;
    if (m0 >= cnt) return;
    int off = d_off[e];
    int n0  = blockIdx.x * 128;
    const float* B = W + (size_t)e * (size_t)K_TOT * N_TOT;

    __shared__ uint32_t AsH[BK][LDS_PAD];
    __shared__ uint32_t AsL[BK][LDS_PAD];
    __shared__ uint32_t BsH[BK][LDS_PAD];
    __shared__ uint32_t BsL[BK][LDS_PAD];

    int tid  = threadIdx.x;
    int lane = tid & 31;
    int w    = tid >> 5;
    int wm   = (w >> 2) * 64;
    int wn   = (w & 3) * 32;
    int gid  = lane >> 2;
    int tg   = lane & 3;

    // staging roles (R1 verbatim)
    int ar = tid >> 1;
    int ak = (tid & 1) * 4;
    int arow_ok = (m0 + ar < cnt);
    const float* arow;
    if (G1) arow = A_in + (size_t)d_tok[off + (arow_ok ? m0 + ar : 0)] * K_TOT;
    else    arow = d_hbuf + (size_t)(off + (arow_ok ? m0 + ar : 0)) * K_TOT;
    int bk = tid >> 5;
    int bn = (tid & 31) * 4;

    float acc[4][4][4];
#pragma unroll
    for (int mt = 0; mt < 4; mt++)
#pragma unroll
        for (int nt = 0; nt < 4; nt++)
#pragma unroll
            for (int j = 0; j < 4; j++) acc[mt][nt][j] = 0.f;

    // register prefetch of chunk 0
    float4 pa0 = *(const float4*)(arow + ak);
    float4 pa1 = *(const float4*)(arow + 8 + ak);
    float4 pb0 = *(const float4*)(B + (size_t)bk * N_TOT + n0 + bn);
    float4 pb1 = *(const float4*)(B + (size_t)(bk + 8) * N_TOT + n0 + bn);

    for (int ch = 0; ch < NCH; ch++) {
        // ---- store prefetched regs to smem, splitting to tf32 hi/lo ----
        {
            float fa[8] = {pa0.x, pa0.y, pa0.z, pa0.w, pa1.x, pa1.y, pa1.z, pa1.w};
#pragma unroll
            for (int j = 0; j < 4; j++) {
                split_tf32(fa[j],     AsH[ak + j][ar],     AsL[ak + j][ar]);
                split_tf32(fa[4 + j], AsH[8 + ak + j][ar], AsL[8 + ak + j][ar]);
            }
            float fb[8] = {pb0.x, pb0.y, pb0.z, pb0.w, pb1.x, pb1.y, pb1.z, pb1.w};
#pragma unroll
            for (int j = 0; j < 4; j++) {
                split_tf32(fb[j],     BsH[bk][bn + j],     BsL[bk][bn + j]);
                split_tf32(fb[4 + j], BsH[bk + 8][bn + j], BsL[bk + 8][bn + j]);
            }
        }
        __syncthreads();

        // ---- prefetch next chunk (overlaps with mma below) ----
        if (ch + 1 < NCH) {
            int k1 = (ch + 1) * BK;
            pa0 = *(const float4*)(arow + k1 + ak);
            pa1 = *(const float4*)(arow + k1 + 8 + ak);
            pb0 = *(const float4*)(B + (size_t)(k1 + bk) * N_TOT + n0 + bn);
            pb1 = *(const float4*)(B + (size_t)(k1 + bk + 8) * N_TOT + n0 + bn);
        }

        // ---- compute: 2 x k8 steps, 3xTF32 ----
#pragma unroll
        for (int s = 0; s < 2; s++) {
            int kb = s * 8;
            uint32_t bh[4][2], bl[4][2];
#pragma unroll
            for (int nt = 0; nt < 4; nt++) {
                int cb = wn + nt * 8 + gid;
                bh[nt][0] = BsH[kb + tg][cb];     bl[nt][0] = BsL[kb + tg][cb];
                bh[nt][1] = BsH[kb + tg + 4][cb]; bl[nt][1] = BsL[kb + tg + 4][cb];
            }
#pragma unroll
            for (int mt = 0; mt < 4; mt++) {
                int ca = wm + mt * 16 + gid;
                uint32_t ah[4], al[4];
                ah[0] = AsH[kb + tg][ca];         al[0] = AsL[kb + tg][ca];
                ah[1] = AsH[kb + tg][ca + 8];     al[1] = AsL[kb + tg][ca + 8];
                ah[2] = AsH[kb + tg + 4][ca];     al[2] = AsL[kb + tg + 4][ca];
                ah[3] = AsH[kb + tg + 4][ca + 8]; al[3] = AsL[kb + tg + 4][ca + 8];
#pragma unroll
                for (int nt = 0; nt < 4; nt++) {
                    mma_tf32(acc[mt][nt], ah, bh[nt][0], bh[nt][1]);
                    mma_tf32(acc[mt][nt], ah, bl[nt][0], bl[nt][1]);
                    mma_tf32(acc[mt][nt], al, bh[nt][0], bh[nt][1]);
                }
            }
        }
        __syncthreads();
    }

    // ---- epilogue ----
    const float* bp = bias + (size_t)e * N_TOT + n0;
#pragma unroll
    for (int mt = 0; mt < 4; mt++) {
#pragma unroll
        for (int half = 0; half < 2; half++) {
            int m = m0 + wm + mt * 16 + gid + half * 8;
            if (m >= cnt) continue;
#pragma unroll
            for (int nt = 0; nt < 4; nt++) {
                int col = wn + nt * 8 + tg * 2;
                float v0 = acc[mt][nt][half * 2 + 0] + bp[col];
                float v1 = acc[mt][nt][half * 2 + 1] + bp[col + 1];
                if (G1) {
                    float2 g;
                    g.x = gelu_tanh(v0);
                    g.y = gelu_tanh(v1);
                    *(float2*)(d_hbuf + (size_t)(off + m) * F_DIM + n0 + col) = g;
                } else {
                    float2 v; v.x = v0; v.y = v1;
                    *(float2*)(d_ybuf + (size_t)(off + m) * H_DIM + n0 + col) = v;
                }
            }
        }
    }
}

__global__ void combine_kernel(float* __restrict__ out) {
    int idx = blockIdx.x * blockDim.x + threadIdx.x;
    if (idx >= T_TOK * (H_DIM / 4)) return;
    int t  = idx >> 8;
    int n4 = idx & 255;
    int   s0 = d_slot[2 * t + 0], s1 = d_slot[2 * t + 1];
    float w0 = d_wt[2 * t + 0],  w1 = d_wt[2 * t + 1];
    float4 a = *(const float4*)(d_ybuf + (size_t)s0 * H_DIM + n4 * 4);
    float4 b = *(const float4*)(d_ybuf + (size_t)s1 * H_DIM + n4 * 4);
    float4 o;
    o.x = w0 * a.x + w1 * b.x;
    o.y = w0 * a.y + w1 * b.y;
    o.z = w0 * a.z + w1 * b.z;
    o.w = w0 * a.w + w1 * b.w;
    *(float4*)(out + (size_t)t * H_DIM + n4 * 4) = o;
}

// ---------------- launch -----------------------------------------------------
extern "C" void kernel_launch(void* const* d_in, const int* in_sizes, int n_in,
                              void* d_out, int out_size) {
    const float* x  = (const float*)d_in[0];
    const float* rw = (const float*)d_in[1];
    const float* rb = (const float*)d_in[2];
    const float* w1 = (const float*)d_in[3];
    const float* b1 = (const float*)d_in[4];
    const float* w2 = (const float*)d_in[5];
    const float* b2 = (const float*)d_in[6];
    float* out = (float*)d_out;

    init_kernel<<<1, 32>>>();
    router_kernel<<<T_TOK / 4, 128>>>(x, rw, rb);
    offsets_kernel<<<1, 32>>>();
    scatter_kernel<<<(T_TOK + 255) / 256, 256>>>();

    dim3 g1(F_DIM / 128, T_TOK / 128, E_NUM);   // (32, 64, 8)
    moe_gemm<true><<<g1, 256>>>(x, w1, b1);
    dim3 g2(H_DIM / 128, T_TOK / 128, E_NUM);   // (8, 64, 8)
    moe_gemm<false><<<g2, 256>>>(x, w2, b2);

    combine_kernel<<<(T_TOK * (H_DIM / 4) + 255) / 256, 256>>>(out);
}

// round 9
// speedup vs baseline: 1.5829x; 1.5829x over previous
#include <cuda_runtime.h>
#include <cuda_bf16.h>
#include <cstdint>
#include <math.h>

#define T_TOK   8192
#define H_DIM   1024
#define F_DIM   4096
#define E_NUM   8
#define A_NUM   (2 * T_TOK)

// ---------------- scratch (known-good R1 set) --------------------------------
__device__ int   d_counts[E_NUM];
__device__ int   d_cursor[E_NUM];
__device__ int   d_off[E_NUM];
__device__ int   d_eidx[A_NUM];
__device__ float d_wt[A_NUM];
__device__ int   d_tok[A_NUM];
__device__ int   d_slot[A_NUM];
__device__ float d_hbuf[(size_t)A_NUM * F_DIM];
__device__ float d_ybuf[(size_t)A_NUM * H_DIM];

// ---------------- PTX --------------------------------------------------------
__device__ __forceinline__ void mma16816(float* c, const uint32_t* a, uint32_t b0, uint32_t b1) {
    asm volatile("mma.sync.aligned.m16n8k16.row.col.f32.bf16.bf16.f32 "
                 "{%0,%1,%2,%3}, {%4,%5,%6,%7}, {%8,%9}, {%0,%1,%2,%3};"
                 : "+f"(c[0]), "+f"(c[1]), "+f"(c[2]), "+f"(c[3])
                 : "r"(a[0]), "r"(a[1]), "r"(a[2]), "r"(a[3]), "r"(b0), "r"(b1));
}
__device__ __forceinline__ unsigned short us_of(__nv_bfloat16 b) { return __bfloat16_as_ushort(b); }
// split two consecutive-k fp32 values into packed bf16x2 hi/lo planes
__device__ __forceinline__ void split2(float x0, float x1, uint32_t& hi, uint32_t& lo) {
    __nv_bfloat16 h0 = __float2bfloat16(x0);
    __nv_bfloat16 h1 = __float2bfloat16(x1);
    float r0 = x0 - __bfloat162float(h0);
    float r1 = x1 - __bfloat162float(h1);
    hi = (uint32_t)us_of(h0) | ((uint32_t)us_of(h1) << 16);
    lo = (uint32_t)us_of(__float2bfloat16(r0)) | ((uint32_t)us_of(__float2bfloat16(r1)) << 16);
}

// ---------------- small kernels (R1 verbatim) --------------------------------
__global__ void init_kernel() {
    int i = threadIdx.x;
    if (i < E_NUM) { d_counts[i] = 0; d_cursor[i] = 0; }
}

__global__ void router_kernel(const float* __restrict__ x,
                              const float* __restrict__ rw,
                              const float* __restrict__ rb) {
    int warp = (blockIdx.x * blockDim.x + threadIdx.x) >> 5;
    int lane = threadIdx.x & 31;
    if (warp >= T_TOK) return;
    const float* xr = x + (size_t)warp * H_DIM;
    float acc[E_NUM];
#pragma unroll
    for (int e = 0; e < E_NUM; e++) acc[e] = 0.f;
    for (int k = lane; k < H_DIM; k += 32) {
        float xv = xr[k];
        const float* r = rw + (size_t)k * E_NUM;
#pragma unroll
        for (int e = 0; e < E_NUM; e++) acc[e] += xv * r[e];
    }
#pragma unroll
    for (int off = 16; off; off >>= 1)
#pragma unroll
        for (int e = 0; e < E_NUM; e++)
            acc[e] += __shfl_down_sync(0xffffffffu, acc[e], off);
    if (lane == 0) {
        float l[E_NUM];
#pragma unroll
        for (int e = 0; e < E_NUM; e++) l[e] = acc[e] + rb[e];
        int i0 = 0;
#pragma unroll
        for (int e = 1; e < E_NUM; e++) if (l[e] > l[i0]) i0 = e;
        int i1 = -1;
#pragma unroll
        for (int e = 0; e < E_NUM; e++)
            if (e != i0 && (i1 < 0 || l[e] > l[i1])) i1 = e;
        float m  = l[i0];
        float p1 = __expf(l[i1] - m);
        float s  = 1.f + p1;
        d_eidx[2 * warp + 0] = i0;  d_wt[2 * warp + 0] = 1.f / s;
        d_eidx[2 * warp + 1] = i1;  d_wt[2 * warp + 1] = p1 / s;
        atomicAdd(&d_counts[i0], 1);
        atomicAdd(&d_counts[i1], 1);
    }
}

__global__ void offsets_kernel() {
    if (threadIdx.x == 0) {
        int acc = 0;
        for (int e = 0; e < E_NUM; e++) { d_off[e] = acc; acc += d_counts[e]; }
    }
}

__global__ void scatter_kernel() {
    int t = blockIdx.x * blockDim.x + threadIdx.x;
    if (t >= T_TOK) return;
#pragma unroll
    for (int j = 0; j < 2; j++) {
        int e   = d_eidx[2 * t + j];
        int pos = d_off[e] + atomicAdd(&d_cursor[e], 1);
        d_tok[pos] = t;
        d_slot[2 * t + j] = pos;
    }
}

// ---------------- grouped GEMM: bf16 m16n8k16 3-term split -------------------
__device__ __forceinline__ float gelu_tanh(float v) {
    float c = 0.7978845608028654f * (v + 0.044715f * v * v * v);
    return 0.5f * v * (1.f + tanhf(c));
}

#define BK      16     // k per chunk = 8 k-pair rows
#define LDS_PAD 136

template <bool G1>
__global__ __launch_bounds__(256, 2) void moe_gemm(const float* __restrict__ A_in,
                                                   const float* __restrict__ W,
                                                   const float* __restrict__ bias) {
    constexpr int K_TOT = G1 ? H_DIM : F_DIM;
    constexpr int N_TOT = G1 ? F_DIM : H_DIM;
    constexpr int NCH   = K_TOT / BK;

    int e   = blockIdx.z;
    int cnt = d_counts[e];
    int m0  = blockIdx.y * 128;
    if (m0 >= cnt) return;
    int off = d_off[e];
    int n0  = blockIdx.x * 128;
    const float* B = W + (size_t)e * (size_t)K_TOT * N_TOT;

    // k-pair rows of packed bf16x2 (lo 16b = even k, hi 16b = odd k)
    __shared__ uint32_t AsH[8][LDS_PAD];
    __shared__ uint32_t AsL[8][LDS_PAD];
    __shared__ uint32_t BsH[8][LDS_PAD];
    __shared__ uint32_t BsL[8][LDS_PAD];

    int tid  = threadIdx.x;
    int lane = tid & 31;
    int w    = tid >> 5;
    int wm   = (w >> 2) * 64;
    int wn   = (w & 3) * 32;
    int gid  = lane >> 2;
    int tg   = lane & 3;

    // A staging roles (R1 verbatim): row ar, consecutive k at ak..ak+3, 8+ak..
    int ar  = tid >> 1;
    int ak  = (tid & 1) * 4;
    int akp = ak >> 1;              // k-pair base: 0 or 2
    int arow_ok = (m0 + ar < cnt);
    const float* arow;
    if (G1) arow = A_in + (size_t)d_tok[off + (arow_ok ? m0 + ar : 0)] * K_TOT;
    else    arow = d_hbuf + (size_t)(off + (arow_ok ? m0 + ar : 0)) * K_TOT;
    // B staging roles: warp bkp handles k-pair rows (2bkp, 2bkp+1), 128 cols
    int bkp = tid >> 5;             // 0..7
    int bn  = (tid & 31) * 4;

    float acc[4][4][4];
#pragma unroll
    for (int mt = 0; mt < 4; mt++)
#pragma unroll
        for (int nt = 0; nt < 4; nt++)
#pragma unroll
            for (int j = 0; j < 4; j++) acc[mt][nt][j] = 0.f;

    // register prefetch of chunk 0
    float4 pa0 = *(const float4*)(arow + ak);
    float4 pa1 = *(const float4*)(arow + 8 + ak);
    float4 pb0 = *(const float4*)(B + (size_t)(2 * bkp) * N_TOT + n0 + bn);
    float4 pb1 = *(const float4*)(B + (size_t)(2 * bkp + 1) * N_TOT + n0 + bn);

    for (int ch = 0; ch < NCH; ch++) {
        // ---- store prefetched regs to smem as packed bf16x2 hi/lo ----
        split2(pa0.x, pa0.y, AsH[akp + 0][ar], AsL[akp + 0][ar]);
        split2(pa0.z, pa0.w, AsH[akp + 1][ar], AsL[akp + 1][ar]);
        split2(pa1.x, pa1.y, AsH[akp + 4][ar], AsL[akp + 4][ar]);
        split2(pa1.z, pa1.w, AsH[akp + 5][ar], AsL[akp + 5][ar]);
        split2(pb0.x, pb1.x, BsH[bkp][bn + 0], BsL[bkp][bn + 0]);
        split2(pb0.y, pb1.y, BsH[bkp][bn + 1], BsL[bkp][bn + 1]);
        split2(pb0.z, pb1.z, BsH[bkp][bn + 2], BsL[bkp][bn + 2]);
        split2(pb0.w, pb1.w, BsH[bkp][bn + 3], BsL[bkp][bn + 3]);
        __syncthreads();

        // ---- prefetch next chunk (overlaps with mma below) ----
        if (ch + 1 < NCH) {
            int k1 = (ch + 1) * BK;
            pa0 = *(const float4*)(arow + k1 + ak);
            pa1 = *(const float4*)(arow + k1 + 8 + ak);
            pb0 = *(const float4*)(B + (size_t)(k1 + 2 * bkp) * N_TOT + n0 + bn);
            pb1 = *(const float4*)(B + (size_t)(k1 + 2 * bkp + 1) * N_TOT + n0 + bn);
        }

        // ---- compute: one k16 step, 3x bf16 split ----
        uint32_t bh[4][2], bl[4][2];
#pragma unroll
        for (int nt = 0; nt < 4; nt++) {
            int cb = wn + nt * 8 + gid;
            bh[nt][0] = BsH[tg][cb];     bl[nt][0] = BsL[tg][cb];
            bh[nt][1] = BsH[tg + 4][cb]; bl[nt][1] = BsL[tg + 4][cb];
        }
#pragma unroll
        for (int mt = 0; mt < 4; mt++) {
            int ca = wm + mt * 16 + gid;
            uint32_t ah[4], al[4];
            ah[0] = AsH[tg][ca];         al[0] = AsL[tg][ca];
            ah[1] = AsH[tg][ca + 8];     al[1] = AsL[tg][ca + 8];
            ah[2] = AsH[tg + 4][ca];     al[2] = AsL[tg + 4][ca];
            ah[3] = AsH[tg + 4][ca + 8]; al[3] = AsL[tg + 4][ca + 8];
#pragma unroll
            for (int nt = 0; nt < 4; nt++) {
                mma16816(acc[mt][nt], ah, bh[nt][0], bh[nt][1]);
                mma16816(acc[mt][nt], ah, bl[nt][0], bl[nt][1]);
                mma16816(acc[mt][nt], al, bh[nt][0], bh[nt][1]);
            }
        }
        __syncthreads();
    }

    // ---- epilogue (same fragment->row/col map as R7, verified) ----
    const float* bp = bias + (size_t)e * N_TOT + n0;
#pragma unroll
    for (int mt = 0; mt < 4; mt++) {
#pragma unroll
        for (int half = 0; half < 2; half++) {
            int m = m0 + wm + mt * 16 + gid + half * 8;
            if (m >= cnt) continue;
#pragma unroll
            for (int nt = 0; nt < 4; nt++) {
                int col = wn + nt * 8 + tg * 2;
                float v0 = acc[mt][nt][half * 2 + 0] + bp[col];
                float v1 = acc[mt][nt][half * 2 + 1] + bp[col + 1];
                if (G1) {
                    float2 g;
                    g.x = gelu_tanh(v0);
                    g.y = gelu_tanh(v1);
                    *(float2*)(d_hbuf + (size_t)(off + m) * F_DIM + n0 + col) = g;
                } else {
                    float2 v; v.x = v0; v.y = v1;
                    *(float2*)(d_ybuf + (size_t)(off + m) * H_DIM + n0 + col) = v;
                }
            }
        }
    }
}

__global__ void combine_kernel(float* __restrict__ out) {
    int idx = blockIdx.x * blockDim.x + threadIdx.x;
    if (idx >= T_TOK * (H_DIM / 4)) return;
    int t  = idx >> 8;
    int n4 = idx & 255;
    int   s0 = d_slot[2 * t + 0], s1 = d_slot[2 * t + 1];
    float w0 = d_wt[2 * t + 0],  w1 = d_wt[2 * t + 1];
    float4 a = *(const float4*)(d_ybuf + (size_t)s0 * H_DIM + n4 * 4);
    float4 b = *(const float4*)(d_ybuf + (size_t)s1 * H_DIM + n4 * 4);
    float4 o;
    o.x = w0 * a.x + w1 * b.x;
    o.y = w0 * a.y + w1 * b.y;
    o.z = w0 * a.z + w1 * b.z;
    o.w = w0 * a.w + w1 * b.w;
    *(float4*)(out + (size_t)t * H_DIM + n4 * 4) = o;
}

// ---------------- launch -----------------------------------------------------
extern "C" void kernel_launch(void* const* d_in, const int* in_sizes, int n_in,
                              void* d_out, int out_size) {
    const float* x  = (const float*)d_in[0];
    const float* rw = (const float*)d_in[1];
    const float* rb = (const float*)d_in[2];
    const float* w1 = (const float*)d_in[3];
    const float* b1 = (const float*)d_in[4];
    const float* w2 = (const float*)d_in[5];
    const float* b2 = (const float*)d_in[6];
    float* out = (float*)d_out;

    init_kernel<<<1, 32>>>();
    router_kernel<<<T_TOK / 4, 128>>>(x, rw, rb);
    offsets_kernel<<<1, 32>>>();
    scatter_kernel<<<(T_TOK + 255) / 256, 256>>>();

    dim3 g1(F_DIM / 128, T_TOK / 128, E_NUM);   // (32, 64, 8)
    moe_gemm<true><<<g1, 256>>>(x, w1, b1);
    dim3 g2(H_DIM / 128, T_TOK / 128, E_NUM);   // (8, 64, 8)
    moe_gemm<false><<<g2, 256>>>(x, w2, b2);

    combine_kernel<<<(T_TOK * (H_DIM / 4) + 255) / 256, 256>>>(out);
}

// round 10
// speedup vs baseline: 1.7373x; 1.0976x over previous
#include <cuda_runtime.h>
#include <cuda_bf16.h>
#include <cstdint>
#include <math.h>

#define T_TOK   8192
#define H_DIM   1024
#define F_DIM   4096
#define E_NUM   8
#define A_NUM   (2 * T_TOK)

// ---------------- scratch (known-good set) -----------------------------------
__device__ int   d_counts[E_NUM];
__device__ int   d_cursor[E_NUM];
__device__ int   d_off[E_NUM];
__device__ int   d_eidx[A_NUM];
__device__ float d_wt[A_NUM];
__device__ int   d_tok[A_NUM];
__device__ int   d_slot[A_NUM];
__device__ float d_hbuf[(size_t)A_NUM * F_DIM];
__device__ float d_ybuf[(size_t)A_NUM * H_DIM];

// ---------------- PTX --------------------------------------------------------
__device__ __forceinline__ void mma16816(float* c, const uint32_t* a, uint32_t b0, uint32_t b1) {
    asm volatile("mma.sync.aligned.m16n8k16.row.col.f32.bf16.bf16.f32 "
                 "{%0,%1,%2,%3}, {%4,%5,%6,%7}, {%8,%9}, {%0,%1,%2,%3};"
                 : "+f"(c[0]), "+f"(c[1]), "+f"(c[2]), "+f"(c[3])
                 : "r"(a[0]), "r"(a[1]), "r"(a[2]), "r"(a[3]), "r"(b0), "r"(b1));
}
// split two consecutive-k fp32 values into packed bf16x2 hi/lo (cheap form)
__device__ __forceinline__ void split2(float x0, float x1, uint32_t& hi, uint32_t& lo) {
    uint32_t h;
    asm("cvt.rn.bf16x2.f32 %0, %1, %2;" : "=r"(h) : "f"(x1), "f"(x0));
    float f0 = __uint_as_float(h << 16);
    float f1 = __uint_as_float(h & 0xFFFF0000u);
    float r0 = x0 - f0;
    float r1 = x1 - f1;
    uint32_t l;
    asm("cvt.rn.bf16x2.f32 %0, %1, %2;" : "=r"(l) : "f"(r1), "f"(r0));
    hi = h; lo = l;
}

// ---------------- small kernels (verbatim) -----------------------------------
__global__ void init_kernel() {
    int i = threadIdx.x;
    if (i < E_NUM) { d_counts[i] = 0; d_cursor[i] = 0; }
}

__global__ void router_kernel(const float* __restrict__ x,
                              const float* __restrict__ rw,
                              const float* __restrict__ rb) {
    int warp = (blockIdx.x * blockDim.x + threadIdx.x) >> 5;
    int lane = threadIdx.x & 31;
    if (warp >= T_TOK) return;
    const float* xr = x + (size_t)warp * H_DIM;
    float acc[E_NUM];
#pragma unroll
    for (int e = 0; e < E_NUM; e++) acc[e] = 0.f;
    for (int k = lane; k < H_DIM; k += 32) {
        float xv = xr[k];
        const float* r = rw + (size_t)k * E_NUM;
#pragma unroll
        for (int e = 0; e < E_NUM; e++) acc[e] += xv * r[e];
    }
#pragma unroll
    for (int off = 16; off; off >>= 1)
#pragma unroll
        for (int e = 0; e < E_NUM; e++)
            acc[e] += __shfl_down_sync(0xffffffffu, acc[e], off);
    if (lane == 0) {
        float l[E_NUM];
#pragma unroll
        for (int e = 0; e < E_NUM; e++) l[e] = acc[e] + rb[e];
        int i0 = 0;
#pragma unroll
        for (int e = 1; e < E_NUM; e++) if (l[e] > l[i0]) i0 = e;
        int i1 = -1;
#pragma unroll
        for (int e = 0; e < E_NUM; e++)
            if (e != i0 && (i1 < 0 || l[e] > l[i1])) i1 = e;
        float m  = l[i0];
        float p1 = __expf(l[i1] - m);
        float s  = 1.f + p1;
        d_eidx[2 * warp + 0] = i0;  d_wt[2 * warp + 0] = 1.f / s;
        d_eidx[2 * warp + 1] = i1;  d_wt[2 * warp + 1] = p1 / s;
        atomicAdd(&d_counts[i0], 1);
        atomicAdd(&d_counts[i1], 1);
    }
}

__global__ void offsets_kernel() {
    if (threadIdx.x == 0) {
        int acc = 0;
        for (int e = 0; e < E_NUM; e++) { d_off[e] = acc; acc += d_counts[e]; }
    }
}

__global__ void scatter_kernel() {
    int t = blockIdx.x * blockDim.x + threadIdx.x;
    if (t >= T_TOK) return;
#pragma unroll
    for (int j = 0; j < 2; j++) {
        int e   = d_eidx[2 * t + j];
        int pos = d_off[e] + atomicAdd(&d_cursor[e], 1);
        d_tok[pos] = t;
        d_slot[2 * t + j] = pos;
    }
}

// ---------------- grouped GEMM: 256x128 block, 64x64 warp, bf16 3-term -------
// Paired-plane smem layout: word(kp, i) at (kp&3)*SLAB + 2*i + (kp>>2)
// A slab 520 words (128... 256 m? A has 256 rows: slab = 256*2+8 = 520)
// B slab 264 words (128 n: 128*2+8)
#define A_SLAB   520
#define A_L_OFF  (4 * A_SLAB)            // 2080
#define B_H_OFF  (8 * A_SLAB)            // 4160
#define B_SLAB   264
#define B_L_OFF  (B_H_OFF + 4 * B_SLAB)  // 5216
#define SMW_TOT  (B_L_OFF + 4 * B_SLAB)  // 6272 words = 25088 B

__device__ __forceinline__ float gelu_tanh(float v) {
    float c = 0.7978845608028654f * (v + 0.044715f * v * v * v);
    return 0.5f * v * (1.f + tanhf(c));
}

template <bool G1>
__global__ __launch_bounds__(256, 1) void moe_gemm(const float* __restrict__ A_in,
                                                   const float* __restrict__ W,
                                                   const float* __restrict__ bias) {
    constexpr int K_TOT = G1 ? H_DIM : F_DIM;
    constexpr int N_TOT = G1 ? F_DIM : H_DIM;
    constexpr int NCH   = K_TOT / 16;

    int e   = blockIdx.z;
    int cnt = d_counts[e];
    int m0  = blockIdx.y * 256;
    if (m0 >= cnt) return;
    int off = d_off[e];
    int n0  = blockIdx.x * 128;
    const float* B = W + (size_t)e * (size_t)K_TOT * N_TOT;

    __shared__ uint32_t smw[SMW_TOT];

    int tid  = threadIdx.x;
    int lane = tid & 31;
    int w    = tid >> 5;
    int wm   = (w >> 1) * 64;       // 4 m-warps x 64
    int wn   = (w & 1) * 64;        // 2 n-warps x 64
    int gid  = lane >> 2;
    int tg   = lane & 3;

    // A staging: thread = row ar (256 rows), 16 consecutive k
    int ar = tid;
    int arow_ok = (m0 + ar < cnt);
    const float* arow;
    if (G1) arow = A_in + (size_t)d_tok[off + (arow_ok ? m0 + ar : 0)] * K_TOT;
    else    arow = d_hbuf + (size_t)(off + (arow_ok ? m0 + ar : 0)) * K_TOT;
    // B staging: tg_s = tid>>6 (kp slab), l64 = tid&63 -> n = l64, l64+64
    int tg_s = tid >> 6;
    int l64  = tid & 63;

    float acc[4][8][4];
#pragma unroll
    for (int mt = 0; mt < 4; mt++)
#pragma unroll
        for (int nt = 0; nt < 8; nt++)
#pragma unroll
            for (int j = 0; j < 4; j++) acc[mt][nt][j] = 0.f;

    // prefetch chunk 0
    float4 pa[4];
    float  pb[8];
#pragma unroll
    for (int j = 0; j < 4; j++) pa[j] = *(const float4*)(arow + 4 * j);
    {
        int rr[4] = {2 * tg_s, 2 * tg_s + 1, 2 * tg_s + 8, 2 * tg_s + 9};
#pragma unroll
        for (int ri = 0; ri < 4; ri++)
#pragma unroll
            for (int j = 0; j < 2; j++)
                pb[ri * 2 + j] = B[(size_t)rr[ri] * N_TOT + n0 + l64 + 64 * j];
    }

    for (int ch = 0; ch < NCH; ch++) {
        // ---- stage prefetched chunk into paired-plane smem ----
        {
            float fa[16] = {pa[0].x, pa[0].y, pa[0].z, pa[0].w,
                            pa[1].x, pa[1].y, pa[1].z, pa[1].w,
                            pa[2].x, pa[2].y, pa[2].z, pa[2].w,
                            pa[3].x, pa[3].y, pa[3].z, pa[3].w};
#pragma unroll
            for (int kq = 0; kq < 4; kq++) {
                uint32_t h0, l0, h1, l1;
                split2(fa[2 * kq],     fa[2 * kq + 1], h0, l0);
                split2(fa[2 * kq + 8], fa[2 * kq + 9], h1, l1);
                *(uint2*)&smw[kq * A_SLAB + 2 * ar]           = make_uint2(h0, h1);
                *(uint2*)&smw[A_L_OFF + kq * A_SLAB + 2 * ar] = make_uint2(l0, l1);
            }
#pragma unroll
            for (int j = 0; j < 2; j++) {
                uint32_t h0, l0, h1, l1;
                split2(pb[0 + j], pb[2 + j], h0, l0);   // kp = tg_s
                split2(pb[4 + j], pb[6 + j], h1, l1);   // kp = tg_s + 4
                int n = l64 + 64 * j;
                *(uint2*)&smw[B_H_OFF + tg_s * B_SLAB + 2 * n] = make_uint2(h0, h1);
                *(uint2*)&smw[B_L_OFF + tg_s * B_SLAB + 2 * n] = make_uint2(l0, l1);
            }
        }
        __syncthreads();

        // ---- prefetch next chunk (overlaps mma) ----
        if (ch + 1 < NCH) {
            int k1 = (ch + 1) * 16;
#pragma unroll
            for (int j = 0; j < 4; j++) pa[j] = *(const float4*)(arow + k1 + 4 * j);
            int rr[4] = {k1 + 2 * tg_s, k1 + 2 * tg_s + 1, k1 + 2 * tg_s + 8, k1 + 2 * tg_s + 9};
#pragma unroll
            for (int ri = 0; ri < 4; ri++)
#pragma unroll
                for (int j = 0; j < 2; j++)
                    pb[ri * 2 + j] = B[(size_t)rr[ri] * N_TOT + n0 + l64 + 64 * j];
        }

        // ---- compute: one k16 step, 64x64 per warp, 3-term split ----
        uint32_t bh[8][2], bl[8][2];
#pragma unroll
        for (int nt = 0; nt < 8; nt++) {
            int cb = wn + nt * 8 + gid;
            uint2 H = *(uint2*)&smw[B_H_OFF + tg * B_SLAB + 2 * cb];
            uint2 L = *(uint2*)&smw[B_L_OFF + tg * B_SLAB + 2 * cb];
            bh[nt][0] = H.x; bh[nt][1] = H.y;
            bl[nt][0] = L.x; bl[nt][1] = L.y;
        }
#pragma unroll
        for (int mt = 0; mt < 4; mt++) {
            int ca = wm + mt * 16 + gid;
            uint2 H0 = *(uint2*)&smw[tg * A_SLAB + 2 * ca];
            uint2 H1 = *(uint2*)&smw[tg * A_SLAB + 2 * (ca + 8)];
            uint2 L0 = *(uint2*)&smw[A_L_OFF + tg * A_SLAB + 2 * ca];
            uint2 L1 = *(uint2*)&smw[A_L_OFF + tg * A_SLAB + 2 * (ca + 8)];
            uint32_t ah[4] = {H0.x, H1.x, H0.y, H1.y};
            uint32_t al[4] = {L0.x, L1.x, L0.y, L1.y};
#pragma unroll
            for (int nt = 0; nt < 8; nt++) {
                mma16816(acc[mt][nt], ah, bh[nt][0], bh[nt][1]);
                mma16816(acc[mt][nt], ah, bl[nt][0], bl[nt][1]);
                mma16816(acc[mt][nt], al, bh[nt][0], bh[nt][1]);
            }
        }
        __syncthreads();
    }

    // ---- epilogue ----
    const float* bp = bias + (size_t)e * N_TOT + n0;
#pragma unroll
    for (int mt = 0; mt < 4; mt++) {
#pragma unroll
        for (int half = 0; half < 2; half++) {
            int m = m0 + wm + mt * 16 + gid + half * 8;
            if (m >= cnt) continue;
#pragma unroll
            for (int nt = 0; nt < 8; nt++) {
                int col = wn + nt * 8 + tg * 2;
                float v0 = acc[mt][nt][half * 2 + 0] + bp[col];
                float v1 = acc[mt][nt][half * 2 + 1] + bp[col + 1];
                if (G1) {
                    float2 g;
                    g.x = gelu_tanh(v0);
                    g.y = gelu_tanh(v1);
                    *(float2*)(d_hbuf + (size_t)(off + m) * F_DIM + n0 + col) = g;
                } else {
                    float2 v; v.x = v0; v.y = v1;
                    *(float2*)(d_ybuf + (size_t)(off + m) * H_DIM + n0 + col) = v;
                }
            }
        }
    }
}

__global__ void combine_kernel(float* __restrict__ out) {
    int idx = blockIdx.x * blockDim.x + threadIdx.x;
    if (idx >= T_TOK * (H_DIM / 4)) return;
    int t  = idx >> 8;
    int n4 = idx & 255;
    int   s0 = d_slot[2 * t + 0], s1 = d_slot[2 * t + 1];
    float w0 = d_wt[2 * t + 0],  w1 = d_wt[2 * t + 1];
    float4 a = *(const float4*)(d_ybuf + (size_t)s0 * H_DIM + n4 * 4);
    float4 b = *(const float4*)(d_ybuf + (size_t)s1 * H_DIM + n4 * 4);
    float4 o;
    o.x = w0 * a.x + w1 * b.x;
    o.y = w0 * a.y + w1 * b.y;
    o.z = w0 * a.z + w1 * b.z;
    o.w = w0 * a.w + w1 * b.w;
    *(float4*)(out + (size_t)t * H_DIM + n4 * 4) = o;
}

// ---------------- launch -----------------------------------------------------
extern "C" void kernel_launch(void* const* d_in, const int* in_sizes, int n_in,
                              void* d_out, int out_size) {
    const float* x  = (const float*)d_in[0];
    const float* rw = (const float*)d_in[1];
    const float* rb = (const float*)d_in[2];
    const float* w1 = (const float*)d_in[3];
    const float* b1 = (const float*)d_in[4];
    const float* w2 = (const float*)d_in[5];
    const float* b2 = (const float*)d_in[6];
    float* out = (float*)d_out;

    init_kernel<<<1, 32>>>();
    router_kernel<<<T_TOK / 4, 128>>>(x, rw, rb);
    offsets_kernel<<<1, 32>>>();
    scatter_kernel<<<(T_TOK + 255) / 256, 256>>>();

    dim3 g1(F_DIM / 128, T_TOK / 256, E_NUM);   // (32, 32, 8)
    moe_gemm<true><<<g1, 256>>>(x, w1, b1);
    dim3 g2(H_DIM / 128, T_TOK / 256, E_NUM);   // (8, 32, 8)
    moe_gemm<false><<<g2, 256>>>(x, w2, b2);

    combine_kernel<<<(T_TOK * (H_DIM / 4) + 255) / 256, 256>>>(out);
}